// round 4
// baseline (speedup 1.0000x reference)
#include <cuda_runtime.h>
#include <cuda_bf16.h>
#include <math.h>
#include <stdint.h>

#define B_ 4096
#define F_ 16
#define H_ 1280
#define N_ 8
#define R_ 64
#define C_ (F_*H_)   // 20480
#define GB 8         // batches per LoRA CTA

// ---------------- device scratch ----------------
__device__ float g_gwinv[N_];
__device__ int   g_expert[B_];
__device__ int   g_cnt[N_];
__device__ int   g_off[N_+1];
__device__ int   g_perm[B_];
__device__ __align__(16) __nv_bfloat16 g_dwhi[N_*R_*H_];
__device__ __align__(16) __nv_bfloat16 g_dwlo[N_*R_*H_];
__device__ __align__(16) __nv_bfloat16 g_uwhi[N_*H_*R_];
__device__ __align__(16) __nv_bfloat16 g_uwlo[N_*H_*R_];

// ---------------- helpers ----------------
__device__ __forceinline__ uint32_t smem_u32(const void* p) {
    uint32_t a;
    asm("{ .reg .u64 t; cvta.to.shared.u64 t, %1; cvt.u32.u64 %0, t; }" : "=r"(a) : "l"(p));
    return a;
}
__device__ __forceinline__ void ldsm_x4(uint32_t* r, uint32_t addr) {
    asm volatile("ldmatrix.sync.aligned.m8n8.x4.shared.b16 {%0,%1,%2,%3}, [%4];"
                 : "=r"(r[0]), "=r"(r[1]), "=r"(r[2]), "=r"(r[3]) : "r"(addr));
}
__device__ __forceinline__ void mma_bf16(float* c, const uint32_t* a, const uint32_t* b) {
    asm volatile("mma.sync.aligned.m16n8k16.row.col.f32.bf16.bf16.f32 "
        "{%0,%1,%2,%3}, {%4,%5,%6,%7}, {%8,%9}, {%0,%1,%2,%3};"
        : "+f"(c[0]), "+f"(c[1]), "+f"(c[2]), "+f"(c[3])
        : "r"(a[0]), "r"(a[1]), "r"(a[2]), "r"(a[3]), "r"(b[0]), "r"(b[1]));
}
__device__ __forceinline__ uint32_t pk(float lo, float hi) {
    uint32_t r;
    asm("cvt.rn.satfinite.bf16x2.f32 %0, %1, %2;" : "=r"(r) : "f"(hi), "f"(lo));
    return r;
}
__device__ __forceinline__ void split2(float a, float b, uint32_t& h, uint32_t& l) {
    h = pk(a, b);
    float fa = __uint_as_float(h << 16);
    float fb = __uint_as_float(h & 0xFFFF0000u);
    l = pk(a - fa, b - fb);
}
__device__ __forceinline__ void cp16(uint32_t s, const void* g) {
    asm volatile("{ .reg .u64 gp; cvta.to.global.u64 gp, %1;"
                 " cp.async.cg.shared.global [%0], [gp], 16; }"
                 :: "r"(s), "l"(g) : "memory");
}
#define CP_COMMIT() asm volatile("cp.async.commit_group;" ::: "memory")
#define CP_WAIT0()  asm volatile("cp.async.wait_group 0;" ::: "memory")

// ================= kw: preconvert dw/uw to bf16 hi/lo =================
__global__ __launch_bounds__(256) void kw(const float* __restrict__ dw,
                                          const float* __restrict__ uw) {
    int i = blockIdx.x * blockDim.x + threadIdx.x;  // 0..163839 float4 units
    float4 v = ((const float4*)dw)[i];
    uint32_t h0, l0, h1, l1;
    split2(v.x, v.y, h0, l0); split2(v.z, v.w, h1, l1);
    ((uint2*)g_dwhi)[i] = make_uint2(h0, h1);
    ((uint2*)g_dwlo)[i] = make_uint2(l0, l1);
    v = ((const float4*)uw)[i];
    split2(v.x, v.y, h0, l0); split2(v.z, v.w, h1, l1);
    ((uint2*)g_uwhi)[i] = make_uint2(h0, h1);
    ((uint2*)g_uwlo)[i] = make_uint2(l0, l1);
}

// ================= k0: gate_w row inverse-norms + reset counters =================
__global__ void k0_prep(const float* __restrict__ gw) {
    int tid = threadIdx.x;
    if (tid < N_) g_cnt[tid] = 0;
    int w = tid >> 5, lane = tid & 31;
    if (w < N_) {
        float s = 0.f;
        const float* row = gw + (size_t)w * C_;
        for (int i = lane; i < C_; i += 32) { float v = row[i]; s += v * v; }
        #pragma unroll
        for (int o = 16; o; o >>= 1) s += __shfl_xor_sync(0xffffffffu, s, o);
        if (lane == 0) g_gwinv[w] = 1.f / fmaxf(sqrtf(s), 1e-12f);
    }
}

// ================= k1: gating dots + fused gumbel-argmax =================
__global__ __launch_bounds__(256) void k1_dots(const float* __restrict__ x,
                                               const float* __restrict__ gw,
                                               const float* __restrict__ u,
                                               const float* __restrict__ sigma_p) {
    __shared__ float xs[32 * 256];
    __shared__ float gws[8 * 256];
    int tid = threadIdx.x;
    int warp = tid >> 5, lane = tid & 31;
    int b0 = blockIdx.x * 32;

    float acc[4][8];
    float sq[4];
    #pragma unroll
    for (int i = 0; i < 4; i++) { sq[i] = 0.f;
        #pragma unroll
        for (int n = 0; n < 8; n++) acc[i][n] = 0.f; }

    const float4* x4g  = (const float4*)x;
    const float4* gw4g = (const float4*)gw;
    float4* xs4  = (float4*)xs;
    float4* gws4 = (float4*)gws;

    for (int ch = 0; ch < C_/256; ch++) {
        int c4 = ch * 64;
        #pragma unroll
        for (int j = 0; j < 2; j++) {
            int i4 = tid + 256*j; int n = i4 >> 6, col = i4 & 63;
            gws4[i4] = gw4g[(size_t)n * (C_/4) + c4 + col];
        }
        #pragma unroll
        for (int j = 0; j < 8; j++) {
            int i4 = tid + 256*j; int b = i4 >> 6, col = i4 & 63;
            xs4[i4] = x4g[(size_t)(b0 + b) * (C_/4) + c4 + col];
        }
        __syncthreads();
        #pragma unroll
        for (int k = 0; k < 2; k++) {
            int fc = k*32 + lane;
            float4 gv[8];
            #pragma unroll
            for (int n = 0; n < 8; n++) gv[n] = gws4[n*64 + fc];
            #pragma unroll
            for (int i = 0; i < 4; i++) {
                float4 xv = xs4[(4*warp + i)*64 + fc];
                sq[i] += xv.x*xv.x + xv.y*xv.y + xv.z*xv.z + xv.w*xv.w;
                #pragma unroll
                for (int n = 0; n < 8; n++)
                    acc[i][n] += xv.x*gv[n].x + xv.y*gv[n].y + xv.z*gv[n].z + xv.w*gv[n].w;
            }
        }
        __syncthreads();
    }
    float sigma = *sigma_p;
    #pragma unroll
    for (int i = 0; i < 4; i++) {
        float s = sq[i];
        #pragma unroll
        for (int o = 16; o; o >>= 1) s += __shfl_xor_sync(0xffffffffu, s, o);
        float dn[8];
        #pragma unroll
        for (int n = 0; n < 8; n++) {
            float d = acc[i][n];
            #pragma unroll
            for (int o = 16; o; o >>= 1) d += __shfl_xor_sync(0xffffffffu, d, o);
            dn[n] = d;
        }
        if (lane == 0) {
            int b = b0 + 4*warp + i;
            float invx = 1.f / fmaxf(sqrtf(s), 1e-12f);
            const float4* u4 = (const float4*)(u + (size_t)b*8);
            float4 ua = u4[0], ub = u4[1];
            float uu[8] = {ua.x, ua.y, ua.z, ua.w, ub.x, ub.y, ub.z, ub.w};
            float best = -3.4e38f; int e = 0;
            #pragma unroll
            for (int n = 0; n < 8; n++) {
                float logit = sigma * dn[n] * invx * g_gwinv[n];
                float gmb = -logf(-logf(uu[n] + 1e-12f) + 1e-12f);
                float z = logit + gmb;
                if (z > best) { best = z; e = n; }
            }
            g_expert[b] = e;
            atomicAdd(&g_cnt[e], 1);
        }
    }
}

// ================= k1cd: scan + scatter (one CTA) =================
__global__ __launch_bounds__(512) void k1cd() {
    __shared__ int cur_s[N_];
    int tid = threadIdx.x;
    if (tid == 0) {
        int a = 0;
        #pragma unroll
        for (int n = 0; n < N_; n++) { g_off[n] = a; cur_s[n] = a; a += g_cnt[n]; }
        g_off[N_] = a;
    }
    __syncthreads();
    for (int b = tid; b < B_; b += 512) {
        int e = g_expert[b];
        int pos = atomicAdd(&cur_s[e], 1);
        g_perm[pos] = b;
    }
}

// ================= K3: pipelined warp-mma grouped LoRA =================
// smem (bytes): X hi/lo double buf, W hi/lo double buf; XOR-swizzled, 128B row stride
#define XHI(b) ((b)*16384)
#define XLO(b) (32768 + (b)*16384)
#define WHI(b) (65536 + (b)*8192)
#define WLO(b) (81920 + (b)*8192)
#define MIDHI 0
#define MIDLO 16384
#define DYN_SMEM 98304

__global__ __launch_bounds__(256, 2)
void k3_mma(const float* __restrict__ x, float* __restrict__ out) {
    extern __shared__ char sm[];
    __shared__ int bs_sh[GB];
    __shared__ int info[2];

    int tid = threadIdx.x, wid = tid >> 5, lid = tid & 31;

    if (tid == 0) {
        int rem = blockIdx.x; int e = -1, g = 0, start = 0;
        for (int n = 0; n < N_; n++) {
            int cnt = g_off[n+1] - g_off[n];
            int ng = (cnt + GB - 1) / GB;
            if (rem < ng) { e = n; start = g_off[n] + rem*GB;
                            g = g_off[n+1] - start; if (g > GB) g = GB; break; }
            rem -= ng;
        }
        info[0] = e; info[1] = g;
        if (e >= 0) for (int i = 0; i < GB; i++) {
            int ii = i < g ? i : g - 1;
            bs_sh[i] = g_perm[start + ii];
        }
    }
    __syncthreads();
    int e = info[0], g = info[1];
    if (e < 0) return;

    uint32_t sb = smem_u32(sm);
    const float4* x4 = (const float4*)x;

    int ldr = tid >> 4;   // x load row base (0..15)
    int ldc = tid & 15;   // x float4 col (0..15)

    // ldmatrix lane geometry
    int arow = 16*wid + (lid & 15);
    uint32_t arow128 = (uint32_t)arow * 128;
    int a_c16b = lid >> 4;
    int brow_[4];
    #pragma unroll
    for (int np = 0; np < 4; np++) brow_[np] = (lid & 7) + ((lid >> 4) & 1)*8 + 16*np;
    int b_c16b = (lid >> 3) & 1;

    // x STS swizzled target offsets (per j computed inline)
    // cp.async unit indices for W tiles (per thread: units tid*2, tid*2+1)
    int wu_row[2], wu_c16[2];
    #pragma unroll
    for (int t = 0; t < 2; t++) { int u = tid*2 + t; wu_row[t] = u >> 3; wu_c16[t] = u & 7; }

    // ---------------- phase 1: mid[128,64] = X @ DW^T ----------------
    float acc[8][4];
    #pragma unroll
    for (int i = 0; i < 8; i++)
        #pragma unroll
        for (int j = 0; j < 4; j++) acc[i][j] = 0.f;

    float4 xg[8];
    size_t dw_base = (size_t)e * 64 * H_;

    // prologue: cp W0, LDG+conv+STS x0, LDG x1
    #pragma unroll
    for (int t = 0; t < 2; t++) {
        uint32_t so = (uint32_t)wu_row[t]*128 + (((wu_c16[t] ^ wu_row[t]) & 7) << 4);
        size_t go = dw_base + (size_t)wu_row[t]*H_ + wu_c16[t]*8;
        cp16(sb + WHI(0) + so, g_dwhi + go);
        cp16(sb + WLO(0) + so, g_dwlo + go);
    }
    CP_COMMIT();
    #pragma unroll
    for (int j = 0; j < 8; j++) {
        int row = ldr + 16*j;
        int bb = bs_sh[row >> 4], f = row & 15;
        xg[j] = x4[(size_t)(bb*16 + f)*320 + ldc];
    }
    #pragma unroll
    for (int j = 0; j < 8; j++) {
        int row = ldr + 16*j;
        uint32_t o = (uint32_t)row*128 + ((((ldc >> 1) ^ row) & 7) << 4) + (ldc & 1)*8;
        uint32_t h0, l0, h1, l1;
        split2(xg[j].x, xg[j].y, h0, l0); split2(xg[j].z, xg[j].w, h1, l1);
        *(uint2*)(sm + XHI(0) + o) = make_uint2(h0, h1);
        *(uint2*)(sm + XLO(0) + o) = make_uint2(l0, l1);
    }
    #pragma unroll
    for (int j = 0; j < 8; j++) {
        int row = ldr + 16*j;
        int bb = bs_sh[row >> 4], f = row & 15;
        xg[j] = x4[(size_t)(bb*16 + f)*320 + 16 + ldc];
    }
    CP_WAIT0();
    __syncthreads();

    for (int ch = 0; ch < 20; ch++) {
        int cur = ch & 1, nxt = cur ^ 1;
        if (ch + 1 < 20) {
            #pragma unroll
            for (int t = 0; t < 2; t++) {
                uint32_t so = (uint32_t)wu_row[t]*128 + (((wu_c16[t] ^ wu_row[t]) & 7) << 4);
                size_t go = dw_base + (size_t)wu_row[t]*H_ + (ch+1)*64 + wu_c16[t]*8;
                cp16(sb + WHI(nxt) + so, g_dwhi + go);
                cp16(sb + WLO(nxt) + so, g_dwlo + go);
            }
            CP_COMMIT();
        }
        // compute chunk ch
        #pragma unroll
        for (int ks = 0; ks < 4; ks++) {
            int ca = 2*ks + a_c16b;
            uint32_t ao = arow128 + (((ca ^ arow) & 7) << 4);
            uint32_t ah[4], al[4];
            ldsm_x4(ah, sb + XHI(cur) + ao);
            ldsm_x4(al, sb + XLO(cur) + ao);
            int cb = 2*ks + b_c16b;
            #pragma unroll
            for (int np = 0; np < 4; np++) {
                uint32_t bo = (uint32_t)brow_[np]*128 + (((cb ^ brow_[np]) & 7) << 4);
                uint32_t bh[4], bl[4];
                ldsm_x4(bh, sb + WHI(cur) + bo);
                ldsm_x4(bl, sb + WLO(cur) + bo);
                mma_bf16(acc[2*np],   ah, bh);
                mma_bf16(acc[2*np],   ah, bl);
                mma_bf16(acc[2*np],   al, bh);
                mma_bf16(acc[2*np+1], ah, bh+2);
                mma_bf16(acc[2*np+1], ah, bl+2);
                mma_bf16(acc[2*np+1], al, bh+2);
            }
        }
        if (ch + 1 < 20) {
            #pragma unroll
            for (int j = 0; j < 8; j++) {
                int row = ldr + 16*j;
                uint32_t o = (uint32_t)row*128 + ((((ldc >> 1) ^ row) & 7) << 4) + (ldc & 1)*8;
                uint32_t h0, l0, h1, l1;
                split2(xg[j].x, xg[j].y, h0, l0); split2(xg[j].z, xg[j].w, h1, l1);
                *(uint2*)(sm + XHI(nxt) + o) = make_uint2(h0, h1);
                *(uint2*)(sm + XLO(nxt) + o) = make_uint2(l0, l1);
            }
            if (ch + 2 < 20) {
                #pragma unroll
                for (int j = 0; j < 8; j++) {
                    int row = ldr + 16*j;
                    int bb = bs_sh[row >> 4], f = row & 15;
                    xg[j] = x4[(size_t)(bb*16 + f)*320 + (ch+2)*16 + ldc];
                }
            }
            CP_WAIT0();
        }
        __syncthreads();
    }

    // ---------------- mid -> smem bf16 hi/lo (warp-local) ----------------
    {
        int r0 = 16*wid + (lid >> 2);
        #pragma unroll
        for (int nt = 0; nt < 8; nt++) {
            uint32_t h, l;
            uint32_t o0 = (uint32_t)r0*128 + (((nt ^ r0) & 7) << 4) + (lid & 3)*4;
            split2(acc[nt][0], acc[nt][1], h, l);
            *(uint32_t*)(sm + MIDHI + o0) = h;
            *(uint32_t*)(sm + MIDLO + o0) = l;
            int r1 = r0 + 8;
            uint32_t o1 = (uint32_t)r1*128 + (((nt ^ r1) & 7) << 4) + (lid & 3)*4;
            split2(acc[nt][2], acc[nt][3], h, l);
            *(uint32_t*)(sm + MIDHI + o1) = h;
            *(uint32_t*)(sm + MIDLO + o1) = l;
        }
    }
    __syncwarp();

    // resident A fragments for phase 2
    uint32_t mah[4][4], mal[4][4];
    #pragma unroll
    for (int ks = 0; ks < 4; ks++) {
        int ca = 2*ks + a_c16b;
        uint32_t ao = arow128 + (((ca ^ arow) & 7) << 4);
        ldsm_x4(mah[ks], sb + MIDHI + ao);
        ldsm_x4(mal[ks], sb + MIDLO + ao);
    }

    // ---------------- phase 2: out = mid @ UW^T (20 h-chunks) ----------------
    size_t uw_base = (size_t)e * H_ * 64;
    int bb_w = bs_sh[wid];
    float* outw = out + (size_t)(bb_w*16)*1280;

    __syncthreads();  // all warps done with phase-1 W buffers before overwrite
    #pragma unroll
    for (int t = 0; t < 2; t++) {
        uint32_t so = (uint32_t)wu_row[t]*128 + (((wu_c16[t] ^ wu_row[t]) & 7) << 4);
        size_t go = uw_base + (size_t)wu_row[t]*64 + wu_c16[t]*8;
        cp16(sb + WHI(0) + so, g_uwhi + go);
        cp16(sb + WLO(0) + so, g_uwlo + go);
    }
    CP_COMMIT();
    CP_WAIT0();
    __syncthreads();

    for (int i = 0; i < 20; i++) {
        int cur = i & 1, nxt = cur ^ 1;
        if (i + 1 < 20) {
            #pragma unroll
            for (int t = 0; t < 2; t++) {
                uint32_t so = (uint32_t)wu_row[t]*128 + (((wu_c16[t] ^ wu_row[t]) & 7) << 4);
                size_t go = uw_base + (size_t)((i+1)*64 + wu_row[t])*64 + wu_c16[t]*8;
                cp16(sb + WHI(nxt) + so, g_uwhi + go);
                cp16(sb + WLO(nxt) + so, g_uwlo + go);
            }
            CP_COMMIT();
        }
        float a2[8][4];
        #pragma unroll
        for (int p = 0; p < 8; p++)
            #pragma unroll
            for (int q = 0; q < 4; q++) a2[p][q] = 0.f;
        #pragma unroll
        for (int ks = 0; ks < 4; ks++) {
            int cb = 2*ks + b_c16b;
            #pragma unroll
            for (int np = 0; np < 4; np++) {
                uint32_t bo = (uint32_t)brow_[np]*128 + (((cb ^ brow_[np]) & 7) << 4);
                uint32_t bh[4], bl[4];
                ldsm_x4(bh, sb + WHI(cur) + bo);
                ldsm_x4(bl, sb + WLO(cur) + bo);
                mma_bf16(a2[2*np],   mah[ks], bh);
                mma_bf16(a2[2*np],   mah[ks], bl);
                mma_bf16(a2[2*np],   mal[ks], bh);
                mma_bf16(a2[2*np+1], mah[ks], bh+2);
                mma_bf16(a2[2*np+1], mah[ks], bl+2);
                mma_bf16(a2[2*np+1], mal[ks], bh+2);
            }
        }
        if (wid < g) {
            int r0 = lid >> 2, c0 = (lid & 3)*2;
            #pragma unroll
            for (int nt = 0; nt < 8; nt++) {
                int col = i*64 + nt*8 + c0;
                *(float2*)(outw + (size_t)r0*1280 + col)     = make_float2(a2[nt][0], a2[nt][1]);
                *(float2*)(outw + (size_t)(r0+8)*1280 + col) = make_float2(a2[nt][2], a2[nt][3]);
            }
        }
        if (i + 1 < 20) CP_WAIT0();
        __syncthreads();
    }
}

// ================= launch =================
extern "C" void kernel_launch(void* const* d_in, const int* in_sizes, int n_in,
                              void* d_out, int out_size) {
    const float* x     = (const float*)d_in[0];
    const float* u     = (const float*)d_in[1];
    const float* gw    = (const float*)d_in[2];
    const float* sigma = (const float*)d_in[3];
    const float* dw    = (const float*)d_in[4];
    const float* uw    = (const float*)d_in[5];
    float* out = (float*)d_out;

    cudaFuncSetAttribute(k3_mma, cudaFuncAttributeMaxDynamicSharedMemorySize, DYN_SMEM);

    kw<<<640, 256>>>(dw, uw);
    k0_prep<<<1, 256>>>(gw);
    k1_dots<<<B_/32, 256>>>(x, gw, u, sigma);
    k1cd<<<1, 512>>>();
    k3_mma<<<B_/GB + N_, 256, DYN_SMEM>>>(x, out);
}

// round 5
// speedup vs baseline: 1.2057x; 1.2057x over previous
#include <cuda_runtime.h>
#include <cuda_fp16.h>
#include <math.h>
#include <stdint.h>

#define B_ 4096
#define F_ 16
#define H_ 1280
#define N_ 8
#define R_ 64
#define C_ (F_*H_)   // 20480
#define GB 8         // batches per LoRA CTA

// ---------------- device scratch ----------------
__device__ float g_gwinv[N_];
__device__ int   g_expert[B_];
__device__ int   g_cnt[N_];
__device__ int   g_off[N_+1];
__device__ int   g_perm[B_];

// ---------------- helpers ----------------
__device__ __forceinline__ uint32_t smem_u32(const void* p) {
    uint32_t a;
    asm("{ .reg .u64 t; cvta.to.shared.u64 t, %1; cvt.u32.u64 %0, t; }" : "=r"(a) : "l"(p));
    return a;
}
__device__ __forceinline__ void ldsm_x4(uint32_t* r, uint32_t addr) {
    asm volatile("ldmatrix.sync.aligned.m8n8.x4.shared.b16 {%0,%1,%2,%3}, [%4];"
                 : "=r"(r[0]), "=r"(r[1]), "=r"(r[2]), "=r"(r[3]) : "r"(addr));
}
__device__ __forceinline__ void mma_f16(float* c, const uint32_t* a, const uint32_t* b) {
    asm volatile("mma.sync.aligned.m16n8k16.row.col.f32.f16.f16.f32 "
        "{%0,%1,%2,%3}, {%4,%5,%6,%7}, {%8,%9}, {%0,%1,%2,%3};"
        : "+f"(c[0]), "+f"(c[1]), "+f"(c[2]), "+f"(c[3])
        : "r"(a[0]), "r"(a[1]), "r"(a[2]), "r"(a[3]), "r"(b[0]), "r"(b[1]));
}
// pack two floats into f16x2 word: lower half = f16(lo), upper half = f16(hi)
__device__ __forceinline__ uint32_t pkh(float lo, float hi) {
    uint32_t r;
    asm("cvt.rn.f16x2.f32 %0, %1, %2;" : "=r"(r) : "f"(hi), "f"(lo));
    return r;
}
__device__ __forceinline__ void split2h(float a, float b, uint32_t& h, uint32_t& l) {
    h = pkh(a, b);
    __half2 hh = *reinterpret_cast<__half2*>(&h);
    float2 f = __half22float2(hh);
    l = pkh(a - f.x, b - f.y);
}
__device__ __forceinline__ void st_hilo(char* hi_p, char* lo_p, float4 v) {
    uint32_t h0, l0, h1, l1;
    split2h(v.x, v.y, h0, l0);
    split2h(v.z, v.w, h1, l1);
    *(uint2*)hi_p = make_uint2(h0, h1);
    *(uint2*)lo_p = make_uint2(l0, l1);
}
__device__ __forceinline__ void st_hi(char* hi_p, float4 v) {
    uint32_t h0 = pkh(v.x, v.y);
    uint32_t h1 = pkh(v.z, v.w);
    *(uint2*)hi_p = make_uint2(h0, h1);
}

// smem byte offsets; row stride 144B (72 halves) -> conflict-free ldmatrix
#define STRD 144
#define X_HI   0
#define X_LO   18432
#define W_HI   36864
#define MID_HI 0
#define MID_LO 18432
#define DYN_SMEM 46080

// ================= k0: gate_w row inverse-norms + reset counters =================
__global__ void k0_prep(const float* __restrict__ gw) {
    int tid = threadIdx.x;
    if (tid < N_) g_cnt[tid] = 0;
    int w = tid >> 5, lane = tid & 31;
    if (w < N_) {
        float s = 0.f;
        const float* row = gw + (size_t)w * C_;
        for (int i = lane; i < C_; i += 32) { float v = row[i]; s += v * v; }
        #pragma unroll
        for (int o = 16; o; o >>= 1) s += __shfl_xor_sync(0xffffffffu, s, o);
        if (lane == 0) g_gwinv[w] = 1.f / fmaxf(sqrtf(s), 1e-12f);
    }
}

// ================= k1: gating dots + fused gumbel-argmax =================
__global__ __launch_bounds__(256) void k1_dots(const float* __restrict__ x,
                                               const float* __restrict__ gw,
                                               const float* __restrict__ u,
                                               const float* __restrict__ sigma_p) {
    __shared__ float xs[32 * 256];
    __shared__ float gws[8 * 256];
    int tid = threadIdx.x;
    int warp = tid >> 5, lane = tid & 31;
    int b0 = blockIdx.x * 32;

    float acc[4][8];
    float sq[4];
    #pragma unroll
    for (int i = 0; i < 4; i++) { sq[i] = 0.f;
        #pragma unroll
        for (int n = 0; n < 8; n++) acc[i][n] = 0.f; }

    const float4* x4g  = (const float4*)x;
    const float4* gw4g = (const float4*)gw;
    float4* xs4  = (float4*)xs;
    float4* gws4 = (float4*)gws;

    for (int ch = 0; ch < C_/256; ch++) {
        int c4 = ch * 64;
        #pragma unroll
        for (int j = 0; j < 2; j++) {
            int i4 = tid + 256*j; int n = i4 >> 6, col = i4 & 63;
            gws4[i4] = gw4g[(size_t)n * (C_/4) + c4 + col];
        }
        #pragma unroll
        for (int j = 0; j < 8; j++) {
            int i4 = tid + 256*j; int b = i4 >> 6, col = i4 & 63;
            xs4[i4] = x4g[(size_t)(b0 + b) * (C_/4) + c4 + col];
        }
        __syncthreads();
        #pragma unroll
        for (int k = 0; k < 2; k++) {
            int fc = k*32 + lane;
            float4 gv[8];
            #pragma unroll
            for (int n = 0; n < 8; n++) gv[n] = gws4[n*64 + fc];
            #pragma unroll
            for (int i = 0; i < 4; i++) {
                float4 xv = xs4[(4*warp + i)*64 + fc];
                sq[i] += xv.x*xv.x + xv.y*xv.y + xv.z*xv.z + xv.w*xv.w;
                #pragma unroll
                for (int n = 0; n < 8; n++)
                    acc[i][n] += xv.x*gv[n].x + xv.y*gv[n].y + xv.z*gv[n].z + xv.w*gv[n].w;
            }
        }
        __syncthreads();
    }
    float sigma = *sigma_p;
    #pragma unroll
    for (int i = 0; i < 4; i++) {
        float s = sq[i];
        #pragma unroll
        for (int o = 16; o; o >>= 1) s += __shfl_xor_sync(0xffffffffu, s, o);
        float dn[8];
        #pragma unroll
        for (int n = 0; n < 8; n++) {
            float d = acc[i][n];
            #pragma unroll
            for (int o = 16; o; o >>= 1) d += __shfl_xor_sync(0xffffffffu, d, o);
            dn[n] = d;
        }
        if (lane == 0) {
            int b = b0 + 4*warp + i;
            float invx = 1.f / fmaxf(sqrtf(s), 1e-12f);
            const float4* u4 = (const float4*)(u + (size_t)b*8);
            float4 ua = u4[0], ub = u4[1];
            float uu[8] = {ua.x, ua.y, ua.z, ua.w, ub.x, ub.y, ub.z, ub.w};
            float best = -3.4e38f; int e = 0;
            #pragma unroll
            for (int n = 0; n < 8; n++) {
                float logit = sigma * dn[n] * invx * g_gwinv[n];
                float gmb = -logf(-logf(uu[n] + 1e-12f) + 1e-12f);
                float z = logit + gmb;
                if (z > best) { best = z; e = n; }
            }
            g_expert[b] = e;
            atomicAdd(&g_cnt[e], 1);
        }
    }
}

// ================= k1cd: scan + scatter (one CTA) =================
__global__ __launch_bounds__(512) void k1cd() {
    __shared__ int cur_s[N_];
    int tid = threadIdx.x;
    if (tid == 0) {
        int a = 0;
        #pragma unroll
        for (int n = 0; n < N_; n++) { g_off[n] = a; cur_s[n] = a; a += g_cnt[n]; }
        g_off[N_] = a;
    }
    __syncthreads();
    for (int b = tid; b < B_; b += 512) {
        int e = g_expert[b];
        int pos = atomicAdd(&cur_s[e], 1);
        g_perm[pos] = b;
    }
}

// ================= K3: warp-mma grouped LoRA (fp16 2-term split) =================
__global__ __launch_bounds__(256, 2)
void k3_mma(const float* __restrict__ x, const float* __restrict__ dw,
            const float* __restrict__ uw, float* __restrict__ out) {
    extern __shared__ char sm[];
    __shared__ int bs_sh[GB];
    __shared__ int info[2];

    int tid = threadIdx.x, wid = tid >> 5, lid = tid & 31;

    if (tid == 0) {
        int rem = blockIdx.x; int e = -1, g = 0, start = 0;
        for (int n = 0; n < N_; n++) {
            int cnt = g_off[n+1] - g_off[n];
            int ng = (cnt + GB - 1) / GB;
            if (rem < ng) { e = n; start = g_off[n] + rem*GB;
                            g = g_off[n+1] - start; if (g > GB) g = GB; break; }
            rem -= ng;
        }
        info[0] = e; info[1] = g;
        if (e >= 0) for (int i = 0; i < GB; i++) {
            int ii = i < g ? i : g - 1;
            bs_sh[i] = g_perm[start + ii];
        }
    }
    __syncthreads();
    int e = info[0], g = info[1];
    if (e < 0) return;

    uint32_t sb = smem_u32(sm);
    const float4* x4  = (const float4*)x;
    const float4* dw4 = (const float4*)dw;
    const float4* uw4 = (const float4*)uw;

    int ldr = tid >> 4;   // load row base (0..15)
    int ldc = tid & 15;   // float4 column (0..15) = 64 floats/row

    // ldmatrix lane address offsets (byte)
    uint32_t aoff = (uint32_t)((16*wid + (lid & 15))*STRD + (lid >> 4)*16);
    uint32_t boff = (uint32_t)(((lid & 7) + ((lid >> 4) & 1)*8)*STRD + ((lid >> 3) & 1)*16);

    // ---------------- phase 1: mid[128,64] = X[128,1280] @ DW[64,1280]^T ----------------
    float acc[8][4];
    #pragma unroll
    for (int i = 0; i < 8; i++)
        #pragma unroll
        for (int j = 0; j < 4; j++) acc[i][j] = 0.f;

    float4 xg[8], wg[4];
    // prologue: load chunk 0
    #pragma unroll
    for (int j = 0; j < 8; j++) {
        int row = ldr + 16*j;
        int bb = bs_sh[row >> 4], f = row & 15;
        xg[j] = x4[(size_t)(bb*16 + f)*320 + ldc];
    }
    #pragma unroll
    for (int j = 0; j < 4; j++) {
        int row = ldr + 16*j;
        wg[j] = dw4[(size_t)(e*64 + row)*320 + ldc];
    }
    #pragma unroll
    for (int j = 0; j < 8; j++) {
        int row = ldr + 16*j;
        st_hilo(sm + X_HI + row*STRD + ldc*8, sm + X_LO + row*STRD + ldc*8, xg[j]);
    }
    #pragma unroll
    for (int j = 0; j < 4; j++) {
        int row = ldr + 16*j;
        st_hi(sm + W_HI + row*STRD + ldc*8, wg[j]);
    }
    __syncthreads();

    for (int ch = 0; ch < 20; ch++) {
        if (ch + 1 < 20) {
            #pragma unroll
            for (int j = 0; j < 8; j++) {
                int row = ldr + 16*j;
                int bb = bs_sh[row >> 4], f = row & 15;
                xg[j] = x4[(size_t)(bb*16 + f)*320 + (ch+1)*16 + ldc];
            }
            #pragma unroll
            for (int j = 0; j < 4; j++) {
                int row = ldr + 16*j;
                wg[j] = dw4[(size_t)(e*64 + row)*320 + (ch+1)*16 + ldc];
            }
        }
        // compute on chunk ch (2-term: ah*b + al*b)
        #pragma unroll
        for (int ks = 0; ks < 4; ks++) {
            uint32_t ah[4], al[4];
            ldsm_x4(ah, sb + X_HI + aoff + ks*32);
            ldsm_x4(al, sb + X_LO + aoff + ks*32);
            #pragma unroll
            for (int np = 0; np < 4; np++) {
                uint32_t bh[4];
                ldsm_x4(bh, sb + W_HI + boff + np*16*STRD + ks*32);
                mma_f16(acc[2*np],   ah, bh);
                mma_f16(acc[2*np],   al, bh);
                mma_f16(acc[2*np+1], ah, bh+2);
                mma_f16(acc[2*np+1], al, bh+2);
            }
        }
        __syncthreads();
        if (ch + 1 < 20) {
            #pragma unroll
            for (int j = 0; j < 8; j++) {
                int row = ldr + 16*j;
                st_hilo(sm + X_HI + row*STRD + ldc*8, sm + X_LO + row*STRD + ldc*8, xg[j]);
            }
            #pragma unroll
            for (int j = 0; j < 4; j++) {
                int row = ldr + 16*j;
                st_hi(sm + W_HI + row*STRD + ldc*8, wg[j]);
            }
            __syncthreads();
        }
    }

    // ---------------- mid -> smem f16 hi/lo ----------------
    {
        int r0 = 16*wid + (lid >> 2);
        int co = (lid & 3)*4;  // byte offset of 2 halves within ntile
        #pragma unroll
        for (int nt = 0; nt < 8; nt++) {
            uint32_t h, l;
            split2h(acc[nt][0], acc[nt][1], h, l);
            *(uint32_t*)(sm + MID_HI + r0*STRD + nt*16 + co) = h;
            *(uint32_t*)(sm + MID_LO + r0*STRD + nt*16 + co) = l;
            split2h(acc[nt][2], acc[nt][3], h, l);
            *(uint32_t*)(sm + MID_HI + (r0+8)*STRD + nt*16 + co) = h;
            *(uint32_t*)(sm + MID_LO + (r0+8)*STRD + nt*16 + co) = l;
        }
    }
    __syncthreads();

    // resident A fragments for phase 2 (K = 64 -> 4 ksteps)
    uint32_t mah[4][4], mal[4][4];
    #pragma unroll
    for (int ks = 0; ks < 4; ks++) {
        ldsm_x4(mah[ks], sb + MID_HI + aoff + ks*32);
        ldsm_x4(mal[ks], sb + MID_LO + aoff + ks*32);
    }

    // ---------------- phase 2: out[128,1280] = mid[128,64] @ UW[1280,64]^T ----------------
    int bb_w = bs_sh[wid];
    float* outw = out + (size_t)(bb_w*16)*1280;

    // prologue: load UW chunk 0
    #pragma unroll
    for (int j = 0; j < 4; j++) {
        int row = ldr + 16*j;
        wg[j] = uw4[(size_t)(e*1280 + row)*16 + ldc];
    }
    __syncthreads();  // mid ldsm done before W region overwrite (aliases nothing, but keep order)
    #pragma unroll
    for (int j = 0; j < 4; j++) {
        int row = ldr + 16*j;
        st_hi(sm + W_HI + row*STRD + ldc*8, wg[j]);
    }
    __syncthreads();

    for (int i = 0; i < 20; i++) {
        if (i + 1 < 20) {
            #pragma unroll
            for (int j = 0; j < 4; j++) {
                int row = ldr + 16*j;
                wg[j] = uw4[(size_t)(e*1280 + (i+1)*64 + row)*16 + ldc];
            }
        }
        float a2[8][4];
        #pragma unroll
        for (int p = 0; p < 8; p++)
            #pragma unroll
            for (int q = 0; q < 4; q++) a2[p][q] = 0.f;
        #pragma unroll
        for (int ks = 0; ks < 4; ks++) {
            #pragma unroll
            for (int np = 0; np < 4; np++) {
                uint32_t bh[4];
                ldsm_x4(bh, sb + W_HI + boff + np*16*STRD + ks*32);
                mma_f16(a2[2*np],   mah[ks], bh);
                mma_f16(a2[2*np],   mal[ks], bh);
                mma_f16(a2[2*np+1], mah[ks], bh+2);
                mma_f16(a2[2*np+1], mal[ks], bh+2);
            }
        }
        // epilogue: direct 32B-sector stores
        if (wid < g) {
            int r0 = lid >> 2, c0 = (lid & 3)*2;
            #pragma unroll
            for (int nt = 0; nt < 8; nt++) {
                int col = i*64 + nt*8 + c0;
                *(float2*)(outw + (size_t)r0*1280 + col)     = make_float2(a2[nt][0], a2[nt][1]);
                *(float2*)(outw + (size_t)(r0+8)*1280 + col) = make_float2(a2[nt][2], a2[nt][3]);
            }
        }
        __syncthreads();
        if (i + 1 < 20) {
            #pragma unroll
            for (int j = 0; j < 4; j++) {
                int row = ldr + 16*j;
                st_hi(sm + W_HI + row*STRD + ldc*8, wg[j]);
            }
            __syncthreads();
        }
    }
}

// ================= launch =================
extern "C" void kernel_launch(void* const* d_in, const int* in_sizes, int n_in,
                              void* d_out, int out_size) {
    const float* x     = (const float*)d_in[0];
    const float* u     = (const float*)d_in[1];
    const float* gw    = (const float*)d_in[2];
    const float* sigma = (const float*)d_in[3];
    const float* dw    = (const float*)d_in[4];
    const float* uw    = (const float*)d_in[5];
    float* out = (float*)d_out;

    cudaFuncSetAttribute(k3_mma, cudaFuncAttributeMaxDynamicSharedMemorySize, DYN_SMEM);

    k0_prep<<<1, 256>>>(gw);
    k1_dots<<<B_/32, 256>>>(x, gw, u, sigma);
    k1cd<<<1, 512>>>();
    k3_mma<<<B_/GB + N_, 256, DYN_SMEM>>>(x, dw, uw, out);
}

// round 6
// speedup vs baseline: 1.4503x; 1.2029x over previous
#include <cuda_runtime.h>
#include <cuda_fp16.h>
#include <math.h>
#include <stdint.h>

#define B_ 4096
#define F_ 16
#define H_ 1280
#define N_ 8
#define R_ 64
#define C_ (F_*H_)   // 20480
#define GB 8         // batches per LoRA CTA

// ---------------- device scratch ----------------
__device__ float g_gwinv[N_];
__device__ float g_dot[B_*N_];
__device__ float g_xsq[B_];
__device__ int   g_expert[B_];
__device__ int   g_cnt[N_];
__device__ int   g_off[N_+1];
__device__ int   g_perm[B_];

// ---------------- helpers ----------------
__device__ __forceinline__ uint32_t smem_u32(const void* p) {
    uint32_t a;
    asm("{ .reg .u64 t; cvta.to.shared.u64 t, %1; cvt.u32.u64 %0, t; }" : "=r"(a) : "l"(p));
    return a;
}
__device__ __forceinline__ void ldsm_x4(uint32_t* r, uint32_t addr) {
    asm volatile("ldmatrix.sync.aligned.m8n8.x4.shared.b16 {%0,%1,%2,%3}, [%4];"
                 : "=r"(r[0]), "=r"(r[1]), "=r"(r[2]), "=r"(r[3]) : "r"(addr));
}
__device__ __forceinline__ void mma_f16(float* c, const uint32_t* a, const uint32_t* b) {
    asm volatile("mma.sync.aligned.m16n8k16.row.col.f32.f16.f16.f32 "
        "{%0,%1,%2,%3}, {%4,%5,%6,%7}, {%8,%9}, {%0,%1,%2,%3};"
        : "+f"(c[0]), "+f"(c[1]), "+f"(c[2]), "+f"(c[3])
        : "r"(a[0]), "r"(a[1]), "r"(a[2]), "r"(a[3]), "r"(b[0]), "r"(b[1]));
}
__device__ __forceinline__ uint32_t pkh(float lo, float hi) {
    uint32_t r;
    asm("cvt.rn.f16x2.f32 %0, %1, %2;" : "=r"(r) : "f"(hi), "f"(lo));
    return r;
}
__device__ __forceinline__ void split2h(float a, float b, uint32_t& h, uint32_t& l) {
    h = pkh(a, b);
    __half2 hh = *reinterpret_cast<__half2*>(&h);
    float2 f = __half22float2(hh);
    l = pkh(a - f.x, b - f.y);
}
__device__ __forceinline__ void st_hilo(char* hi_p, char* lo_p, float4 v) {
    uint32_t h0, l0, h1, l1;
    split2h(v.x, v.y, h0, l0);
    split2h(v.z, v.w, h1, l1);
    *(uint2*)hi_p = make_uint2(h0, h1);
    *(uint2*)lo_p = make_uint2(l0, l1);
}
__device__ __forceinline__ void st_hi(char* hi_p, float4 v) {
    uint32_t h0 = pkh(v.x, v.y);
    uint32_t h1 = pkh(v.z, v.w);
    *(uint2*)hi_p = make_uint2(h0, h1);
}

// smem byte offsets; row stride 144B (72 halves) -> conflict-free ldmatrix
#define STRD 144
#define X_HI   0
#define X_LO   18432
#define W_HI   36864
#define MID_HI 0
#define MID_LO 18432
#define DYN_SMEM 46080

// ================= k0: zero accumulators + gwinv + reset counters =================
__global__ void k0_prep(const float* __restrict__ gw) {
    int tid = threadIdx.x;
    int cta = blockIdx.x;
    if (cta < 32) {
        #pragma unroll
        for (int j = 0; j < 4; j++) g_dot[cta*1024 + tid + 256*j] = 0.f;
        if (cta < 16) g_xsq[cta*256 + tid] = 0.f;
        return;
    }
    // cta == 32: gwinv + counters
    if (tid < N_) g_cnt[tid] = 0;
    int w = tid >> 5, lane = tid & 31;
    if (w < N_) {
        float s = 0.f;
        const float* row = gw + (size_t)w * C_;
        for (int i = lane; i < C_; i += 32) { float v = row[i]; s += v * v; }
        #pragma unroll
        for (int o = 16; o; o >>= 1) s += __shfl_xor_sync(0xffffffffu, s, o);
        if (lane == 0) g_gwinv[w] = 1.f / fmaxf(sqrtf(s), 1e-12f);
    }
}

// ================= k1: gating dots via fp16 3-term mma, K-split 16 =================
// grid (32, 16): x = M-tile of 128 batches, y = K-split of 1280 cols (20 chunks of 64)
__global__ __launch_bounds__(256) void k1_mma(const float* __restrict__ x,
                                              const float* __restrict__ gw) {
    __shared__ char sm[36864 + 2*2304];   // X hi/lo + W hi/lo (16 padded rows)
    const int W_LO_O = 36864 + 2304;

    int tid = threadIdx.x, wid = tid >> 5, lid = tid & 31;
    int b0 = blockIdx.x * 128;
    int kb = blockIdx.y;        // 0..15

    uint32_t sb = smem_u32(sm);
    const float4* x4  = (const float4*)x;
    const float4* gw4 = (const float4*)gw;

    int ldr = tid >> 4;   // x row base (0..15)
    int ldc = tid & 15;   // float4 col (0..15)

    uint32_t aoff = (uint32_t)((16*wid + (lid & 15))*STRD + (lid >> 4)*16);
    uint32_t boff = (uint32_t)(((lid & 7) + ((lid >> 4) & 1)*8)*STRD + ((lid >> 3) & 1)*16);

    float acc[4] = {0.f, 0.f, 0.f, 0.f};
    float sqr[8];
    #pragma unroll
    for (int j = 0; j < 8; j++) sqr[j] = 0.f;

    float4 xg[8], wg;
    // prologue: load + convert chunk 0
    #pragma unroll
    for (int j = 0; j < 8; j++) {
        int row = ldr + 16*j;
        xg[j] = x4[(size_t)(b0 + row)*5120 + kb*320 + ldc];
    }
    if (tid < 128) wg = gw4[(size_t)(tid >> 4)*5120 + kb*320 + (tid & 15)];
    #pragma unroll
    for (int j = 0; j < 8; j++) {
        int row = ldr + 16*j;
        sqr[j] += xg[j].x*xg[j].x + xg[j].y*xg[j].y + xg[j].z*xg[j].z + xg[j].w*xg[j].w;
        st_hilo(sm + X_HI + row*STRD + ldc*8, sm + X_LO + row*STRD + ldc*8, xg[j]);
    }
    if (tid < 128)
        st_hilo(sm + W_HI + (tid >> 4)*STRD + (tid & 15)*8,
                sm + W_LO_O + (tid >> 4)*STRD + (tid & 15)*8, wg);
    __syncthreads();

    for (int ch = 0; ch < 20; ch++) {
        if (ch + 1 < 20) {
            #pragma unroll
            for (int j = 0; j < 8; j++) {
                int row = ldr + 16*j;
                xg[j] = x4[(size_t)(b0 + row)*5120 + kb*320 + (ch+1)*16 + ldc];
            }
            if (tid < 128) wg = gw4[(size_t)(tid >> 4)*5120 + kb*320 + (ch+1)*16 + (tid & 15)];
        }
        #pragma unroll
        for (int ks = 0; ks < 4; ks++) {
            uint32_t ah[4], al[4], bh[4], bl[4];
            ldsm_x4(ah, sb + X_HI + aoff + ks*32);
            ldsm_x4(al, sb + X_LO + aoff + ks*32);
            ldsm_x4(bh, sb + W_HI + boff + ks*32);
            ldsm_x4(bl, sb + W_LO_O + boff + ks*32);
            mma_f16(acc, ah, bh);
            mma_f16(acc, al, bh);
            mma_f16(acc, ah, bl);
        }
        __syncthreads();
        if (ch + 1 < 20) {
            #pragma unroll
            for (int j = 0; j < 8; j++) {
                int row = ldr + 16*j;
                sqr[j] += xg[j].x*xg[j].x + xg[j].y*xg[j].y + xg[j].z*xg[j].z + xg[j].w*xg[j].w;
                st_hilo(sm + X_HI + row*STRD + ldc*8, sm + X_LO + row*STRD + ldc*8, xg[j]);
            }
            if (tid < 128)
                st_hilo(sm + W_HI + (tid >> 4)*STRD + (tid & 15)*8,
                        sm + W_LO_O + (tid >> 4)*STRD + (tid & 15)*8, wg);
            __syncthreads();
        }
    }

    // ---- xsq: reduce across the 16 threads sharing ldr (offsets < 16 stay in group) ----
    #pragma unroll
    for (int j = 0; j < 8; j++) {
        float s = sqr[j];
        #pragma unroll
        for (int o = 8; o; o >>= 1) s += __shfl_xor_sync(0xffffffffu, s, o);
        sqr[j] = s;
    }
    if ((tid & 15) == 0) {
        #pragma unroll
        for (int j = 0; j < 8; j++)
            atomicAdd(&g_xsq[b0 + ldr + 16*j], sqr[j]);
    }

    // ---- dots: mma accumulator lane map -> atomicAdd ----
    {
        int r = lid >> 2, n0 = 2*(lid & 3);
        int m0 = b0 + wid*16 + r;
        atomicAdd(&g_dot[(size_t)m0*8 + n0],       acc[0]);
        atomicAdd(&g_dot[(size_t)m0*8 + n0 + 1],   acc[1]);
        atomicAdd(&g_dot[(size_t)(m0+8)*8 + n0],   acc[2]);
        atomicAdd(&g_dot[(size_t)(m0+8)*8 + n0+1], acc[3]);
    }
}

// ================= k1b: logits + gumbel + argmax =================
__global__ void k1b_argmax(const float* __restrict__ u, const float* __restrict__ sigma_p) {
    int b = blockIdx.x * blockDim.x + threadIdx.x;
    if (b >= B_) return;
    float sigma = *sigma_p;
    float invx = 1.f / fmaxf(sqrtf(g_xsq[b]), 1e-12f);
    const float4* u4 = (const float4*)(u + (size_t)b*8);
    float4 ua = u4[0], ub = u4[1];
    float uu[8] = {ua.x, ua.y, ua.z, ua.w, ub.x, ub.y, ub.z, ub.w};
    float best = -3.4e38f; int e = 0;
    #pragma unroll
    for (int n = 0; n < 8; n++) {
        float logit = sigma * g_dot[(size_t)b*8 + n] * invx * g_gwinv[n];
        float gmb = -logf(-logf(uu[n] + 1e-12f) + 1e-12f);
        float z = logit + gmb;
        if (z > best) { best = z; e = n; }
    }
    g_expert[b] = e;
    atomicAdd(&g_cnt[e], 1);
}

// ================= k1cd: scan + scatter (one CTA) =================
__global__ __launch_bounds__(512) void k1cd() {
    __shared__ int cur_s[N_];
    int tid = threadIdx.x;
    if (tid == 0) {
        int a = 0;
        #pragma unroll
        for (int n = 0; n < N_; n++) { g_off[n] = a; cur_s[n] = a; a += g_cnt[n]; }
        g_off[N_] = a;
    }
    __syncthreads();
    for (int b = tid; b < B_; b += 512) {
        int e = g_expert[b];
        int pos = atomicAdd(&cur_s[e], 1);
        g_perm[pos] = b;
    }
}

// ================= K3: warp-mma grouped LoRA (fp16 2-term split) — unchanged =================
__global__ __launch_bounds__(256, 2)
void k3_mma(const float* __restrict__ x, const float* __restrict__ dw,
            const float* __restrict__ uw, float* __restrict__ out) {
    extern __shared__ char sm[];
    __shared__ int bs_sh[GB];
    __shared__ int info[2];

    int tid = threadIdx.x, wid = tid >> 5, lid = tid & 31;

    if (tid == 0) {
        int rem = blockIdx.x; int e = -1, g = 0, start = 0;
        for (int n = 0; n < N_; n++) {
            int cnt = g_off[n+1] - g_off[n];
            int ng = (cnt + GB - 1) / GB;
            if (rem < ng) { e = n; start = g_off[n] + rem*GB;
                            g = g_off[n+1] - start; if (g > GB) g = GB; break; }
            rem -= ng;
        }
        info[0] = e; info[1] = g;
        if (e >= 0) for (int i = 0; i < GB; i++) {
            int ii = i < g ? i : g - 1;
            bs_sh[i] = g_perm[start + ii];
        }
    }
    __syncthreads();
    int e = info[0], g = info[1];
    if (e < 0) return;

    uint32_t sb = smem_u32(sm);
    const float4* x4  = (const float4*)x;
    const float4* dw4 = (const float4*)dw;
    const float4* uw4 = (const float4*)uw;

    int ldr = tid >> 4;
    int ldc = tid & 15;

    uint32_t aoff = (uint32_t)((16*wid + (lid & 15))*STRD + (lid >> 4)*16);
    uint32_t boff = (uint32_t)(((lid & 7) + ((lid >> 4) & 1)*8)*STRD + ((lid >> 3) & 1)*16);

    // ---------------- phase 1 ----------------
    float acc[8][4];
    #pragma unroll
    for (int i = 0; i < 8; i++)
        #pragma unroll
        for (int j = 0; j < 4; j++) acc[i][j] = 0.f;

    float4 xg[8], wg[4];
    #pragma unroll
    for (int j = 0; j < 8; j++) {
        int row = ldr + 16*j;
        int bb = bs_sh[row >> 4], f = row & 15;
        xg[j] = x4[(size_t)(bb*16 + f)*320 + ldc];
    }
    #pragma unroll
    for (int j = 0; j < 4; j++) {
        int row = ldr + 16*j;
        wg[j] = dw4[(size_t)(e*64 + row)*320 + ldc];
    }
    #pragma unroll
    for (int j = 0; j < 8; j++) {
        int row = ldr + 16*j;
        st_hilo(sm + X_HI + row*STRD + ldc*8, sm + X_LO + row*STRD + ldc*8, xg[j]);
    }
    #pragma unroll
    for (int j = 0; j < 4; j++) {
        int row = ldr + 16*j;
        st_hi(sm + W_HI + row*STRD + ldc*8, wg[j]);
    }
    __syncthreads();

    for (int ch = 0; ch < 20; ch++) {
        if (ch + 1 < 20) {
            #pragma unroll
            for (int j = 0; j < 8; j++) {
                int row = ldr + 16*j;
                int bb = bs_sh[row >> 4], f = row & 15;
                xg[j] = x4[(size_t)(bb*16 + f)*320 + (ch+1)*16 + ldc];
            }
            #pragma unroll
            for (int j = 0; j < 4; j++) {
                int row = ldr + 16*j;
                wg[j] = dw4[(size_t)(e*64 + row)*320 + (ch+1)*16 + ldc];
            }
        }
        #pragma unroll
        for (int ks = 0; ks < 4; ks++) {
            uint32_t ah[4], al[4];
            ldsm_x4(ah, sb + X_HI + aoff + ks*32);
            ldsm_x4(al, sb + X_LO + aoff + ks*32);
            #pragma unroll
            for (int np = 0; np < 4; np++) {
                uint32_t bh[4];
                ldsm_x4(bh, sb + W_HI + boff + np*16*STRD + ks*32);
                mma_f16(acc[2*np],   ah, bh);
                mma_f16(acc[2*np],   al, bh);
                mma_f16(acc[2*np+1], ah, bh+2);
                mma_f16(acc[2*np+1], al, bh+2);
            }
        }
        __syncthreads();
        if (ch + 1 < 20) {
            #pragma unroll
            for (int j = 0; j < 8; j++) {
                int row = ldr + 16*j;
                st_hilo(sm + X_HI + row*STRD + ldc*8, sm + X_LO + row*STRD + ldc*8, xg[j]);
            }
            #pragma unroll
            for (int j = 0; j < 4; j++) {
                int row = ldr + 16*j;
                st_hi(sm + W_HI + row*STRD + ldc*8, wg[j]);
            }
            __syncthreads();
        }
    }

    // ---------------- mid -> smem f16 hi/lo ----------------
    {
        int r0 = 16*wid + (lid >> 2);
        int co = (lid & 3)*4;
        #pragma unroll
        for (int nt = 0; nt < 8; nt++) {
            uint32_t h, l;
            split2h(acc[nt][0], acc[nt][1], h, l);
            *(uint32_t*)(sm + MID_HI + r0*STRD + nt*16 + co) = h;
            *(uint32_t*)(sm + MID_LO + r0*STRD + nt*16 + co) = l;
            split2h(acc[nt][2], acc[nt][3], h, l);
            *(uint32_t*)(sm + MID_HI + (r0+8)*STRD + nt*16 + co) = h;
            *(uint32_t*)(sm + MID_LO + (r0+8)*STRD + nt*16 + co) = l;
        }
    }
    __syncthreads();

    uint32_t mah[4][4], mal[4][4];
    #pragma unroll
    for (int ks = 0; ks < 4; ks++) {
        ldsm_x4(mah[ks], sb + MID_HI + aoff + ks*32);
        ldsm_x4(mal[ks], sb + MID_LO + aoff + ks*32);
    }

    // ---------------- phase 2 ----------------
    int bb_w = bs_sh[wid];
    float* outw = out + (size_t)(bb_w*16)*1280;

    #pragma unroll
    for (int j = 0; j < 4; j++) {
        int row = ldr + 16*j;
        wg[j] = uw4[(size_t)(e*1280 + row)*16 + ldc];
    }
    __syncthreads();
    #pragma unroll
    for (int j = 0; j < 4; j++) {
        int row = ldr + 16*j;
        st_hi(sm + W_HI + row*STRD + ldc*8, wg[j]);
    }
    __syncthreads();

    for (int i = 0; i < 20; i++) {
        if (i + 1 < 20) {
            #pragma unroll
            for (int j = 0; j < 4; j++) {
                int row = ldr + 16*j;
                wg[j] = uw4[(size_t)(e*1280 + (i+1)*64 + row)*16 + ldc];
            }
        }
        float a2[8][4];
        #pragma unroll
        for (int p = 0; p < 8; p++)
            #pragma unroll
            for (int q = 0; q < 4; q++) a2[p][q] = 0.f;
        #pragma unroll
        for (int ks = 0; ks < 4; ks++) {
            #pragma unroll
            for (int np = 0; np < 4; np++) {
                uint32_t bh[4];
                ldsm_x4(bh, sb + W_HI + boff + np*16*STRD + ks*32);
                mma_f16(a2[2*np],   mah[ks], bh);
                mma_f16(a2[2*np],   mal[ks], bh);
                mma_f16(a2[2*np+1], mah[ks], bh+2);
                mma_f16(a2[2*np+1], mal[ks], bh+2);
            }
        }
        if (wid < g) {
            int r0 = lid >> 2, c0 = (lid & 3)*2;
            #pragma unroll
            for (int nt = 0; nt < 8; nt++) {
                int col = i*64 + nt*8 + c0;
                *(float2*)(outw + (size_t)r0*1280 + col)     = make_float2(a2[nt][0], a2[nt][1]);
                *(float2*)(outw + (size_t)(r0+8)*1280 + col) = make_float2(a2[nt][2], a2[nt][3]);
            }
        }
        __syncthreads();
        if (i + 1 < 20) {
            #pragma unroll
            for (int j = 0; j < 4; j++) {
                int row = ldr + 16*j;
                st_hi(sm + W_HI + row*STRD + ldc*8, wg[j]);
            }
            __syncthreads();
        }
    }
}

// ================= launch =================
extern "C" void kernel_launch(void* const* d_in, const int* in_sizes, int n_in,
                              void* d_out, int out_size) {
    const float* x     = (const float*)d_in[0];
    const float* u     = (const float*)d_in[1];
    const float* gw    = (const float*)d_in[2];
    const float* sigma = (const float*)d_in[3];
    const float* dw    = (const float*)d_in[4];
    const float* uw    = (const float*)d_in[5];
    float* out = (float*)d_out;

    cudaFuncSetAttribute(k3_mma, cudaFuncAttributeMaxDynamicSharedMemorySize, DYN_SMEM);

    k0_prep<<<33, 256>>>(gw);
    k1_mma<<<dim3(32, 16), 256>>>(x, gw);
    k1b_argmax<<<B_/256, 256>>>(u, sigma);
    k1cd<<<1, 512>>>();
    k3_mma<<<B_/GB + N_, 256, DYN_SMEM>>>(x, dw, uw, out);
}